// round 13
// baseline (speedup 1.0000x reference)
#include <cuda_runtime.h>
#include <cuda_fp16.h>

#define NUSERS 100000
#define NITEMS 50000
#define NENT   120000
#define DIM    64
#define NREL   32
#define NEDGES 1000000
#define NCF    1000000
#define HOPS   2
#define MAX_ITER 3

// ---------------- persistent device scratch (no allocations) ----------------
__device__ __align__(16) float g_ent0[NENT*DIM];
__device__ __align__(16) float g_ent1[NENT*DIM];
__device__ __align__(16) float g_usr [NUSERS*DIM];
__device__ __align__(16) float g_ucf [NUSERS*DIM];
__device__ __align__(16) float g_icfA[NITEMS*DIM];
__device__ __align__(16) float g_icfB[NITEMS*DIM];
__device__ __align__(16) float g_agg1[NENT*DIM];   // cross mean
__device__ __align__(16) float g_agg2[NENT*DIM];   // same mean
// fused fp16 CF table: per item, 192 halves = [rik(64) | icf(64) | item_kg(64)]
__device__ __align__(16) __half g_cf16[NITEMS*3*DIM];

// CSR structures (rebuilt every launch; input-dependent)
__device__ int g_hcnt[NENT];       __device__ int g_hcur[NENT];
__device__ int g_rcnt[NITEMS];     __device__ int g_rcur[NITEMS];
__device__ int g_ccnt[NITEMS];     __device__ int g_ccur[NITEMS];
__device__ int g_hoff[NENT+1];
__device__ int g_roff[NITEMS+1];
__device__ int g_coff[NITEMS+1];
__device__ int g_ecsr[NEDGES];     // tail | (type<<17)
__device__ int g_rcsr[NCF];        // col, grouped by row
__device__ int g_ccsr[NCF];        // row, grouped by col
__device__ int g_part[128];

// cross-group (offsets 8,16) butterfly allreduce
__device__ __forceinline__ float xgrp(float v) {
    v += __shfl_xor_sync(0xffffffffu, v, 8);
    v += __shfl_xor_sync(0xffffffffu, v, 16);
    return v;
}
__device__ __forceinline__ float4 xgrp4(float4 v) {
    v.x = xgrp(v.x); v.y = xgrp(v.y); v.z = xgrp(v.z); v.w = xgrp(v.w);
    return v;
}

// 8 packed halves (uint4) -> 8 floats
__device__ __forceinline__ void h8f(uint4 v, float* f) {
    const __half2* h = (const __half2*)&v;
    float2 t;
    t = __half22float2(h[0]); f[0] = t.x; f[1] = t.y;
    t = __half22float2(h[1]); f[2] = t.x; f[3] = t.y;
    t = __half22float2(h[2]); f[4] = t.x; f[5] = t.y;
    t = __half22float2(h[3]); f[6] = t.x; f[7] = t.y;
}
// 8 floats -> packed uint4 of half2
__device__ __forceinline__ uint4 f8h(const float* f) {
    uint4 v;
    __half2* h = (__half2*)&v;
    h[0] = __floats2half2_rn(f[0], f[1]);
    h[1] = __floats2half2_rn(f[2], f[3]);
    h[2] = __floats2half2_rn(f[4], f[5]);
    h[3] = __floats2half2_rn(f[6], f[7]);
    return v;
}

// ---------------- init -------------------------------------------------------
__global__ void init_kernel(const float* __restrict__ user_emb,
                            const float* __restrict__ entity_emb,
                            const float* __restrict__ emb_cf,
                            float* __restrict__ out) {
    int idx = blockIdx.x*blockDim.x + threadIdx.x;
    const int A = NENT*DIM;
    const int B = A + NUSERS*DIM;
    const int C = B + NUSERS*DIM;
    const int E = C + NITEMS*DIM;
    if (idx >= E) return;
    float v;
    if (idx < A)      { v = entity_emb[idx];            g_ent0[idx]  = v; }
    else if (idx < B) { int j = idx - A; v = user_emb[j];            g_usr[j]  = v; }
    else if (idx < C) { int j = idx - B; v = emb_cf[j];              g_ucf[j]  = v; }
    else              { int j = idx - C; v = emb_cf[NUSERS*DIM + j]; g_icfA[j] = v; }
    out[idx] = v;
}

// ---------------- CSR build --------------------------------------------------
__global__ void zero_cnt_kernel() {
    int i = blockIdx.x*blockDim.x + threadIdx.x;
    if (i < NENT)   { g_hcnt[i] = 0; g_hcur[i] = 0; }
    if (i < NITEMS) { g_rcnt[i] = 0; g_rcur[i] = 0; g_ccnt[i] = 0; g_ccur[i] = 0; }
}

__global__ void hist_edges_kernel(const int* __restrict__ eidx) {
    int e = blockIdx.x*blockDim.x + threadIdx.x;
    if (e >= NEDGES) return;
    atomicAdd(&g_hcnt[eidx[e]], 1);
}

__global__ void hist_imat_kernel(const int* __restrict__ imat) {
    int e = blockIdx.x*blockDim.x + threadIdx.x;
    if (e >= NCF) return;
    atomicAdd(&g_rcnt[imat[2*e]], 1);
    atomicAdd(&g_ccnt[imat[2*e+1]], 1);
}

__global__ void scan1_kernel(const int* __restrict__ cnt, int* __restrict__ off, int n) {
    __shared__ int sm[1024];
    int t = threadIdx.x, i = blockIdx.x*1024 + t;
    int v = (i < n) ? cnt[i] : 0;
    sm[t] = v; __syncthreads();
    #pragma unroll
    for (int d = 1; d < 1024; d <<= 1) {
        int x = (t >= d) ? sm[t-d] : 0;
        __syncthreads();
        sm[t] += x;
        __syncthreads();
    }
    if (i < n) off[i] = sm[t] - v;
    if (t == 1023) g_part[blockIdx.x] = sm[1023];
}

__global__ void scan2_kernel(int nb) {
    __shared__ int sm[128];
    int t = threadIdx.x;
    int v = (t < nb) ? g_part[t] : 0;
    sm[t] = v; __syncthreads();
    #pragma unroll
    for (int d = 1; d < 128; d <<= 1) {
        int x = (t >= d) ? sm[t-d] : 0;
        __syncthreads();
        sm[t] += x;
        __syncthreads();
    }
    if (t < nb) g_part[t] = sm[t] - v;
}

__global__ void scan3_kernel(int* __restrict__ off, int n, int total) {
    int i = blockIdx.x*1024 + threadIdx.x;
    if (i < n) off[i] += g_part[blockIdx.x];
    if (i == 0) off[n] = total;
}

__global__ void fill_edges_kernel(const int* __restrict__ eidx,
                                  const int* __restrict__ etype) {
    int e = blockIdx.x*blockDim.x + threadIdx.x;
    if (e >= NEDGES) return;
    int head = eidx[e];
    int tail = eidx[NEDGES + e];
    int t    = etype[e];
    int pos = g_hoff[head] + atomicAdd(&g_hcur[head], 1);
    g_ecsr[pos] = tail | (t << 17);
}

__global__ void fill_imat_kernel(const int* __restrict__ imat) {
    int e = blockIdx.x*blockDim.x + threadIdx.x;
    if (e >= NCF) return;
    int row = imat[2*e], col = imat[2*e+1];
    g_rcsr[g_roff[row] + atomicAdd(&g_rcur[row], 1)] = col;
    g_ccsr[g_coff[col] + atomicAdd(&g_ccur[col], 1)] = row;
}

// ---------------- KG aggregation + cf16 pack: warp/head, relw in smem -------
// agg1 = cross-mean(tv*rv), agg2 = same-mean(tv+rv);
// item heads also emit fp16 [rik | icf | kg] into g_cf16 (pack fused here).
__global__ void kg_gather_kernel(const float* __restrict__ ent_in,
                                 const float* __restrict__ relw,
                                 const float* __restrict__ icf_cur) {
    __shared__ float srel[NREL*DIM];
    for (int i = threadIdx.x; i < NREL*DIM; i += blockDim.x) srel[i] = relw[i];
    __syncthreads();
    int h = (blockIdx.x*blockDim.x + threadIdx.x) >> 5;
    if (h >= NENT) return;
    int lane = threadIdx.x & 31;
    int g  = lane >> 3;
    int sl = lane & 7;
    int start = g_hoff[h], end = g_hoff[h+1];
    bool hitem = (h < NITEMS);
    float4 a10 = {0,0,0,0}, a11 = {0,0,0,0};
    float4 a20 = {0,0,0,0}, a21 = {0,0,0,0};
    float4 rs0 = {0,0,0,0}, rs1 = {0,0,0,0};
    float cw = 0.f, sw = 0.f;
    for (int i = start + g; i < end; i += 4) {
        int packed = g_ecsr[i];
        int tail = packed & 0x1FFFF;
        int typ  = packed >> 17;
        const float* tp = ent_in + (size_t)tail*DIM + sl*8;
        const float* rp = srel   + typ*DIM + sl*8;
        float4 tv0 = *(const float4*)tp;
        float4 tv1 = *(const float4*)(tp + 4);
        float4 rv0 = *(const float4*)rp;
        float4 rv1 = *(const float4*)(rp + 4);
        bool cross = hitem != (tail < NITEMS);
        if (cross) {
            a10.x += tv0.x*rv0.x; a10.y += tv0.y*rv0.y; a10.z += tv0.z*rv0.z; a10.w += tv0.w*rv0.w;
            a11.x += tv1.x*rv1.x; a11.y += tv1.y*rv1.y; a11.z += tv1.z*rv1.z; a11.w += tv1.w*rv1.w;
            cw += 1.f;
        } else {
            a20.x += tv0.x+rv0.x; a20.y += tv0.y+rv0.y; a20.z += tv0.z+rv0.z; a20.w += tv0.w+rv0.w;
            a21.x += tv1.x+rv1.x; a21.y += tv1.y+rv1.y; a21.z += tv1.z+rv1.z; a21.w += tv1.w+rv1.w;
            sw += 1.f;
        }
        if (hitem) {
            rs0.x += rv0.x; rs0.y += rv0.y; rs0.z += rv0.z; rs0.w += rv0.w;
            rs1.x += rv1.x; rs1.y += rv1.y; rs1.z += rv1.z; rs1.w += rv1.w;
        }
    }
    __syncwarp();
    a10 = xgrp4(a10); a11 = xgrp4(a11);
    a20 = xgrp4(a20); a21 = xgrp4(a21);
    cw = xgrp(cw); sw = xgrp(sw);
    size_t base = (size_t)h*DIM + sl*8;
    if (g == 0) {
        float icw = 1.f / fmaxf(cw, 1.f);
        *(float4*)(g_agg1 + base)     = make_float4(a10.x*icw, a10.y*icw, a10.z*icw, a10.w*icw);
        *(float4*)(g_agg1 + base + 4) = make_float4(a11.x*icw, a11.y*icw, a11.z*icw, a11.w*icw);
    } else if (g == 1) {
        float isw = 1.f / fmaxf(sw, 1.f);
        *(float4*)(g_agg2 + base)     = make_float4(a20.x*isw, a20.y*isw, a20.z*isw, a20.w*isw);
        *(float4*)(g_agg2 + base + 4) = make_float4(a21.x*isw, a21.y*isw, a21.z*isw, a21.w*isw);
    }
    if (hitem) {
        rs0 = xgrp4(rs0); rs1 = xgrp4(rs1);
        __half* cp = g_cf16 + (size_t)h*3*DIM + sl*8;
        if (g == 2) {
            // rik = rel_mean * ent_in[h]; icf passthrough
            float ic = 1.f / fmaxf((float)(end - start), 1.f);
            float4 e0 = *(const float4*)(ent_in + base);
            float4 e1 = *(const float4*)(ent_in + base + 4);
            float rk[8] = { rs0.x*ic*e0.x, rs0.y*ic*e0.y, rs0.z*ic*e0.z, rs0.w*ic*e0.w,
                            rs1.x*ic*e1.x, rs1.y*ic*e1.y, rs1.z*ic*e1.z, rs1.w*ic*e1.w };
            *(uint4*)cp = f8h(rk);
            float4 i0 = *(const float4*)(icf_cur + base);
            float4 i1 = *(const float4*)(icf_cur + base + 4);
            float iv[8] = { i0.x, i0.y, i0.z, i0.w, i1.x, i1.y, i1.z, i1.w };
            *(uint4*)(cp + DIM) = f8h(iv);
        } else if (g == 3) {
            float4 e0 = *(const float4*)(ent_in + base);
            float4 e1 = *(const float4*)(ent_in + base + 4);
            float kv[8] = { e0.x, e0.y, e0.z, e0.w, e1.x, e1.y, e1.z, e1.w };
            *(uint4*)(cp + 2*DIM) = f8h(kv);
        }
    }
}

// ---------------- entity transform + norm -----------------------------------
__global__ void entity_kernel(float* __restrict__ ent_out,
                              const float* __restrict__ W1, const float* __restrict__ b1,
                              const float* __restrict__ W2, const float* __restrict__ b2,
                              float* __restrict__ out_ent) {
    __shared__ float W1t[DIM*DIM];
    __shared__ float W2t[DIM*DIM];
    __shared__ float b1s[DIM], b2s[DIM];
    __shared__ float a1s[4][DIM], a2s[4][DIM];
    __shared__ float part[4][2];
    for (int i = threadIdx.x; i < DIM*DIM; i += blockDim.x) {
        int d = i >> 6, k = i & 63;
        W1t[k*DIM + d] = W1[i];
        W2t[k*DIM + d] = W2[i];
    }
    if (threadIdx.x < DIM) { b1s[threadIdx.x] = b1[threadIdx.x];
                             b2s[threadIdx.x] = b2[threadIdx.x]; }
    __syncthreads();
    int sub = threadIdx.x >> 6;
    int d   = threadIdx.x & 63;
    for (int g = blockIdx.x; g < NENT/4; g += gridDim.x) {
        int e = g*4 + sub;
        a1s[sub][d] = g_agg1[(size_t)e*DIM + d];
        a2s[sub][d] = g_agg2[(size_t)e*DIM + d];
        __syncthreads();
        float o1 = b1s[d], o2 = b2s[d];
        #pragma unroll
        for (int k = 0; k < DIM; k++) {
            o1 += a1s[sub][k] * W1t[k*DIM + d];
            o2 += a2s[sub][k] * W2t[k*DIM + d];
        }
        o1 = (o1 > 0.f) ? o1 : 0.01f*o1;
        o2 = (o2 > 0.f) ? o2 : 0.01f*o2;
        float val = 0.5f*(o1 + o2);
        float ss = val*val;
        #pragma unroll
        for (int off = 16; off; off >>= 1) ss += __shfl_xor_sync(0xffffffffu, ss, off);
        if ((threadIdx.x & 31) == 0) part[sub][d >> 5] = ss;
        __syncthreads();
        float tot = part[sub][0] + part[sub][1];
        float nv  = val / fmaxf(sqrtf(tot), 1e-12f);
        ent_out[(size_t)e*DIM + d]  = nv;
        out_ent[(size_t)e*DIM + d] += nv;
        __syncthreads();
    }
}

// ---------------- item mean+norm: warp/item ---------------------------------
__global__ void item_gather_kernel(float* __restrict__ icf_next,
                                   float* __restrict__ out_icf) {
    int it = (blockIdx.x*blockDim.x + threadIdx.x) >> 5;
    if (it >= NITEMS) return;
    int lane = threadIdx.x & 31;
    int g  = lane >> 3;
    int sl = lane & 7;
    int start = g_coff[it], end = g_coff[it+1];
    float4 a0 = {0,0,0,0}, a1 = {0,0,0,0};
    for (int i = start + g; i < end; i += 4) {
        int row = g_ccsr[i];
        const float* up = g_ucf + (size_t)row*DIM + sl*8;
        float4 u0 = *(const float4*)up;
        float4 u1 = *(const float4*)(up + 4);
        a0.x += u0.x; a0.y += u0.y; a0.z += u0.z; a0.w += u0.w;
        a1.x += u1.x; a1.y += u1.y; a1.z += u1.z; a1.w += u1.w;
    }
    __syncwarp();
    a0 = xgrp4(a0); a1 = xgrp4(a1);
    float ic = 1.f / fmaxf((float)(end - start), 1.f);
    a0.x *= ic; a0.y *= ic; a0.z *= ic; a0.w *= ic;
    a1.x *= ic; a1.y *= ic; a1.z *= ic; a1.w *= ic;
    float ss = a0.x*a0.x + a0.y*a0.y + a0.z*a0.z + a0.w*a0.w
             + a1.x*a1.x + a1.y*a1.y + a1.z*a1.z + a1.w*a1.w;
    ss += __shfl_xor_sync(0xffffffffu, ss, 1);
    ss += __shfl_xor_sync(0xffffffffu, ss, 2);
    ss += __shfl_xor_sync(0xffffffffu, ss, 4);
    float inv = 1.f / fmaxf(sqrtf(ss), 1e-12f);
    float4 n0 = make_float4(a0.x*inv, a0.y*inv, a0.z*inv, a0.w*inv);
    float4 n1 = make_float4(a1.x*inv, a1.y*inv, a1.z*inv, a1.w*inv);
    size_t base = (size_t)it*DIM + sl*8;
    if (g == 0) {
        *(float4*)(icf_next + base)     = n0;
        *(float4*)(icf_next + base + 4) = n1;
    } else if (g == 1) {
        float4 o0 = *(const float4*)(out_icf + base);
        float4 o1 = *(const float4*)(out_icf + base + 4);
        *(float4*)(out_icf + base)     = make_float4(o0.x+n0.x, o0.y+n0.y, o0.z+n0.z, o0.w+n0.w);
        *(float4*)(out_icf + base + 4) = make_float4(o1.x+n1.x, o1.y+n1.y, o1.z+n1.z, o1.w+n1.w);
    }
}

// ---------------- fused CF: warp/user, all 3 iterations, 2-way edge unroll --
__global__ void cf_all_kernel(float* __restrict__ outU,
                              float* __restrict__ outC) {
    int u = (blockIdx.x*blockDim.x + threadIdx.x) >> 5;
    if (u >= NITEMS) return;
    int lane = threadIdx.x & 31;
    int g  = lane >> 3;
    int sl = lane & 7;
    unsigned gmask = 0xFFu << (g*8);
    int start = g_roff[u], end = g_roff[u+1];
    size_t ubase = (size_t)u*DIM + sl*8;
    float uf[8], cf[8];
    {
        float4 t0 = *(const float4*)(g_usr + ubase);
        float4 t1 = *(const float4*)(g_usr + ubase + 4);
        uf[0]=t0.x; uf[1]=t0.y; uf[2]=t0.z; uf[3]=t0.w;
        uf[4]=t1.x; uf[5]=t1.y; uf[6]=t1.z; uf[7]=t1.w;
        t0 = *(const float4*)(g_ucf + ubase);
        t1 = *(const float4*)(g_ucf + ubase + 4);
        cf[0]=t0.x; cf[1]=t0.y; cf[2]=t0.z; cf[3]=t0.w;
        cf[4]=t1.x; cf[5]=t1.y; cf[6]=t1.z; cf[7]=t1.w;
    }
    for (int iter = 0; iter < MAX_ITER; iter++) {
        float s1 = 0.f, s2 = 0.f;
        float a1[8] = {0,0,0,0,0,0,0,0};
        float a2[8] = {0,0,0,0,0,0,0,0};
        int i = start + g;
        // 2-way unrolled: two independent load/dot/exp chains in flight
        for (; i + 4 < end; i += 8) {
            int colA = g_rcsr[i];
            int colB = g_rcsr[i + 4];
            const __half* cpA = g_cf16 + (size_t)colA*3*DIM + sl*8;
            const __half* cpB = g_cf16 + (size_t)colB*3*DIM + sl*8;
            uint4 hrkA = *(const uint4*)cpA;
            uint4 hicA = *(const uint4*)(cpA + DIM);
            uint4 hkgA = *(const uint4*)(cpA + 2*DIM);
            uint4 hrkB = *(const uint4*)cpB;
            uint4 hicB = *(const uint4*)(cpB + DIM);
            uint4 hkgB = *(const uint4*)(cpB + 2*DIM);
            float rkA[8], icA[8], kgA[8], rkB[8], icB[8], kgB[8];
            h8f(hrkA, rkA); h8f(hicA, icA); h8f(hkgA, kgA);
            h8f(hrkB, rkB); h8f(hicB, icB); h8f(hkgB, kgB);
            float d1A = 0.f, d2A = 0.f, d1B = 0.f, d2B = 0.f;
            #pragma unroll
            for (int k = 0; k < 8; k++) {
                d1A += uf[k]*rkA[k]; d2A += cf[k]*icA[k];
                d1B += uf[k]*rkB[k]; d2B += cf[k]*icB[k];
            }
            d1A += __shfl_xor_sync(gmask, d1A, 1); d2A += __shfl_xor_sync(gmask, d2A, 1);
            d1B += __shfl_xor_sync(gmask, d1B, 1); d2B += __shfl_xor_sync(gmask, d2B, 1);
            d1A += __shfl_xor_sync(gmask, d1A, 2); d2A += __shfl_xor_sync(gmask, d2A, 2);
            d1B += __shfl_xor_sync(gmask, d1B, 2); d2B += __shfl_xor_sync(gmask, d2B, 2);
            d1A += __shfl_xor_sync(gmask, d1A, 4); d2A += __shfl_xor_sync(gmask, d2A, 4);
            d1B += __shfl_xor_sync(gmask, d1B, 4); d2B += __shfl_xor_sync(gmask, d2B, 4);
            float w1A = __expf(1.f / (1.f + __expf(-d1A)));
            float w2A = __expf(1.f / (1.f + __expf(-d2A)));
            float w1B = __expf(1.f / (1.f + __expf(-d1B)));
            float w2B = __expf(1.f / (1.f + __expf(-d2B)));
            s1 += w1A + w1B; s2 += w2A + w2B;
            #pragma unroll
            for (int k = 0; k < 8; k++) {
                a1[k] += w1A*kgA[k] + w1B*kgB[k];
                a2[k] += w2A*icA[k] + w2B*icB[k];
            }
        }
        if (i < end) {
            int col = g_rcsr[i];
            const __half* cp = g_cf16 + (size_t)col*3*DIM + sl*8;
            uint4 hrk = *(const uint4*)cp;
            uint4 hic = *(const uint4*)(cp + DIM);
            uint4 hkg = *(const uint4*)(cp + 2*DIM);
            float rk[8], icv[8], kg[8];
            h8f(hrk, rk); h8f(hic, icv); h8f(hkg, kg);
            float d1 = 0.f, d2 = 0.f;
            #pragma unroll
            for (int k = 0; k < 8; k++) { d1 += uf[k]*rk[k]; d2 += cf[k]*icv[k]; }
            d1 += __shfl_xor_sync(gmask, d1, 1);  d2 += __shfl_xor_sync(gmask, d2, 1);
            d1 += __shfl_xor_sync(gmask, d1, 2);  d2 += __shfl_xor_sync(gmask, d2, 2);
            d1 += __shfl_xor_sync(gmask, d1, 4);  d2 += __shfl_xor_sync(gmask, d2, 4);
            float w1 = __expf(1.f / (1.f + __expf(-d1)));
            float w2 = __expf(1.f / (1.f + __expf(-d2)));
            s1 += w1; s2 += w2;
            #pragma unroll
            for (int k = 0; k < 8; k++) { a1[k] += w1*kg[k]; a2[k] += w2*icv[k]; }
        }
        __syncwarp();
        #pragma unroll
        for (int k = 0; k < 8; k++) { a1[k] = xgrp(a1[k]); a2[k] = xgrp(a2[k]); }
        s1 = xgrp(s1); s2 = xgrp(s2);
        float i1 = (end > start) ? 1.f/s1 : 0.f;
        float i2 = (end > start) ? 1.f/s2 : 0.f;
        float ss1 = 0.f, ss2 = 0.f;
        #pragma unroll
        for (int k = 0; k < 8; k++) {
            a1[k] *= i1; a2[k] *= i2;
            ss1 += a1[k]*a1[k]; ss2 += a2[k]*a2[k];
        }
        ss1 += __shfl_xor_sync(0xffffffffu, ss1, 1);  ss2 += __shfl_xor_sync(0xffffffffu, ss2, 1);
        ss1 += __shfl_xor_sync(0xffffffffu, ss1, 2);  ss2 += __shfl_xor_sync(0xffffffffu, ss2, 2);
        ss1 += __shfl_xor_sync(0xffffffffu, ss1, 4);  ss2 += __shfl_xor_sync(0xffffffffu, ss2, 4);
        float n1 = 1.f / fmaxf(sqrtf(ss1), 1e-12f);
        float n2 = 1.f / fmaxf(sqrtf(ss2), 1e-12f);
        #pragma unroll
        for (int k = 0; k < 8; k++) { uf[k] = a1[k]*n1; cf[k] = a2[k]*n2; }
    }
    float4 r0 = make_float4(uf[0], uf[1], uf[2], uf[3]);
    float4 r1 = make_float4(uf[4], uf[5], uf[6], uf[7]);
    float4 c0 = make_float4(cf[0], cf[1], cf[2], cf[3]);
    float4 c1 = make_float4(cf[4], cf[5], cf[6], cf[7]);
    if (g == 0) {
        *(float4*)(g_usr + ubase)     = r0;
        *(float4*)(g_usr + ubase + 4) = r1;
    } else if (g == 1) {
        *(float4*)(g_ucf + ubase)     = c0;
        *(float4*)(g_ucf + ubase + 4) = c1;
    } else if (g == 2) {
        float4 o0 = *(const float4*)(outU + ubase);
        float4 o1 = *(const float4*)(outU + ubase + 4);
        *(float4*)(outU + ubase)     = make_float4(o0.x+r0.x, o0.y+r0.y, o0.z+r0.z, o0.w+r0.w);
        *(float4*)(outU + ubase + 4) = make_float4(o1.x+r1.x, o1.y+r1.y, o1.z+r1.z, o1.w+r1.w);
    } else {
        float4 o0 = *(const float4*)(outC + ubase);
        float4 o1 = *(const float4*)(outC + ubase + 4);
        *(float4*)(outC + ubase)     = make_float4(o0.x+c0.x, o0.y+c0.y, o0.z+c0.z, o0.w+c0.w);
        *(float4*)(outC + ubase + 4) = make_float4(o1.x+c1.x, o1.y+c1.y, o1.z+c1.z, o1.w+c1.w);
    }
}

// ---------------- host orchestration ----------------------------------------
extern "C" void kernel_launch(void* const* d_in, const int* in_sizes, int n_in,
                              void* d_out, int out_size) {
    const float* user_emb   = (const float*)d_in[0];
    const float* entity_emb = (const float*)d_in[1];
    const float* emb_cf     = (const float*)d_in[2];
    const float* relw       = (const float*)d_in[3];
    const float* W1w        = (const float*)d_in[4];
    const float* W1b        = (const float*)d_in[5];
    const float* W2w        = (const float*)d_in[6];
    const float* W2b        = (const float*)d_in[7];
    const int*   eidx       = (const int*)d_in[8];
    const int*   etype      = (const int*)d_in[9];
    const int*   imat       = (const int*)d_in[10];
    float* out = (float*)d_out;
    float* out_usr = out + (size_t)NENT*DIM;
    float* out_ucf = out + (size_t)(NENT + NUSERS)*DIM;
    float* out_icf = out + (size_t)(NENT + 2*NUSERS)*DIM;
    (void)in_sizes; (void)n_in; (void)out_size;

    int *hoff, *roff, *coff, *hcnt, *rcnt, *ccnt;
    cudaGetSymbolAddress((void**)&hoff, g_hoff);
    cudaGetSymbolAddress((void**)&roff, g_roff);
    cudaGetSymbolAddress((void**)&coff, g_coff);
    cudaGetSymbolAddress((void**)&hcnt, g_hcnt);
    cudaGetSymbolAddress((void**)&rcnt, g_rcnt);
    cudaGetSymbolAddress((void**)&ccnt, g_ccnt);
    float *ent0, *ent1, *icfA, *icfB;
    cudaGetSymbolAddress((void**)&ent0, g_ent0);
    cudaGetSymbolAddress((void**)&ent1, g_ent1);
    cudaGetSymbolAddress((void**)&icfA, g_icfA);
    cudaGetSymbolAddress((void**)&icfB, g_icfB);

    const int TOT = (NENT + 2*NUSERS + NITEMS)*DIM;
    init_kernel<<<(TOT + 255)/256, 256>>>(user_emb, entity_emb, emb_cf, out);

    // ---- CSR build (once per launch) ----
    zero_cnt_kernel<<<(NENT + 255)/256, 256>>>();
    hist_edges_kernel<<<(NEDGES + 255)/256, 256>>>(eidx);
    hist_imat_kernel<<<(NCF + 255)/256, 256>>>(imat);
    const int NB_H = (NENT   + 1023)/1024;
    const int NB_I = (NITEMS + 1023)/1024;
    scan1_kernel<<<NB_H, 1024>>>(hcnt, hoff, NENT);
    scan2_kernel<<<1, 128>>>(NB_H);
    scan3_kernel<<<NB_H, 1024>>>(hoff, NENT, NEDGES);
    scan1_kernel<<<NB_I, 1024>>>(rcnt, roff, NITEMS);
    scan2_kernel<<<1, 128>>>(NB_I);
    scan3_kernel<<<NB_I, 1024>>>(roff, NITEMS, NCF);
    scan1_kernel<<<NB_I, 1024>>>(ccnt, coff, NITEMS);
    scan2_kernel<<<1, 128>>>(NB_I);
    scan3_kernel<<<NB_I, 1024>>>(coff, NITEMS, NCF);
    fill_edges_kernel<<<(NEDGES + 255)/256, 256>>>(eidx, etype);
    fill_imat_kernel<<<(NCF + 255)/256, 256>>>(imat);

    for (int h = 0; h < HOPS; h++) {
        float* ent_in   = h ? ent1 : ent0;
        float* ent_next = h ? ent0 : ent1;
        float* icf_cur  = h ? icfB : icfA;
        float* icf_next = h ? icfA : icfB;
        kg_gather_kernel<<<(NENT*32 + 255)/256, 256>>>(ent_in, relw, icf_cur);
        entity_kernel<<<2048, 256>>>(ent_next, W1w + h*DIM*DIM, W1b + h*DIM,
                                     W2w + h*DIM*DIM, W2b + h*DIM, out);
        item_gather_kernel<<<(NITEMS*32 + 255)/256, 256>>>(icf_next, out_icf);
        cf_all_kernel<<<(NITEMS*32 + 255)/256, 256>>>(out_usr, out_ucf);
    }
}